// round 4
// baseline (speedup 1.0000x reference)
#include <cuda_runtime.h>
#include <math.h>

#define NQ   32
#define MM   32
#define ND_  200
#define NN   160
#define HH   768
#define DIMV 128
#define NEGV (-10000.0f)

// Scratch (no cudaMalloc allowed): projected+normalized embeddings.
__device__ float g_Qp[NQ * MM * DIMV];     // 0.5 MB
__device__ float g_Dp[ND_ * NN * DIMV];    // 16.4 MB

// ---------------------------------------------------------------------------
// Projection + row L2-normalize: Y[r,:] = l2norm(X[r,:] @ W), W is HHxDIMV.
// Block computes 64 full rows (DIMV=128 columns each). rows % 64 == 0.
// Thread layout: mg = tid>>4 (16 groups of 4 rows), ng = tid&15 (8 cols each,
// strided by 16 for conflict-free smem reads).
// ---------------------------------------------------------------------------
__global__ __launch_bounds__(256) void proj_kernel(
    const float* __restrict__ X, const float* __restrict__ W,
    float* __restrict__ Y)
{
    __shared__ float Xs[64][33];     // +1 pad
    __shared__ float Ws[32][128];

    const int tid  = threadIdx.x;
    const int mg   = tid >> 4;       // 0..15
    const int ng   = tid & 15;       // 0..15
    const int row0 = blockIdx.x * 64;

    float acc[4][8];
#pragma unroll
    for (int i = 0; i < 4; i++)
#pragma unroll
        for (int j = 0; j < 8; j++) acc[i][j] = 0.0f;

    for (int kt = 0; kt < HH; kt += 32) {
        // Xs: 64x32 = 2048 elems, 8 per thread. One warp covers one row's 32 k.
#pragma unroll
        for (int t = 0; t < 8; t++) {
            int idx = tid + 256 * t;
            int r = idx >> 5, k = idx & 31;
            Xs[r][k] = X[(size_t)(row0 + r) * HH + kt + k];
        }
        // Ws: 32x128 = 4096 elems, 16 per thread, coalesced over n.
#pragma unroll
        for (int t = 0; t < 16; t++) {
            int idx = tid + 256 * t;
            int k = idx >> 7, n = idx & 127;
            Ws[k][n] = W[(size_t)(kt + k) * DIMV + n];
        }
        __syncthreads();

#pragma unroll
        for (int k = 0; k < 32; k++) {
            float a[4], b[8];
#pragma unroll
            for (int i = 0; i < 4; i++) a[i] = Xs[mg * 4 + i][k];
#pragma unroll
            for (int j = 0; j < 8; j++) b[j] = Ws[k][ng + 16 * j];
#pragma unroll
            for (int i = 0; i < 4; i++)
#pragma unroll
                for (int j = 0; j < 8; j++)
                    acc[i][j] = fmaf(a[i], b[j], acc[i][j]);
        }
        __syncthreads();
    }

    // Row L2 norm: each row's 128 cols live across the 16 threads sharing mg,
    // which form one half-warp -> shfl_xor over offsets 8..1 stays in-group.
#pragma unroll
    for (int i = 0; i < 4; i++) {
        float ss = 0.0f;
#pragma unroll
        for (int j = 0; j < 8; j++) ss += acc[i][j] * acc[i][j];
#pragma unroll
        for (int off = 8; off >= 1; off >>= 1)
            ss += __shfl_xor_sync(0xffffffffu, ss, off);
        float inv = 1.0f / fmaxf(sqrtf(ss), 1e-12f);
        int r = row0 + mg * 4 + i;
#pragma unroll
        for (int j = 0; j < 8; j++)
            Y[(size_t)r * DIMV + ng + 16 * j] = acc[i][j] * inv;
    }
}

// ---------------------------------------------------------------------------
// Fused scoring kernel: one block per (q,d) pair.
//   sim = Qp[q] (32x128) @ Dp[d]^T (160x128)   -- fp32, in registers
//   masked: s = sim*dm + (1-dm)*NEG            -- exact select (dm in {0,1})
//   n* = argmax_n (s*10 + gumbel)              -- TEMP=0.1; LSE/TAU drop out
//   out[q,d] = sum_m q_mask[q,m] * s[m, n*]
// Thread layout: warp = m-group (4 rows), lane owns n = lane*5 + j (j<5).
// Dp smem stride 129 (odd) -> 5*129 = 645 ≡ 5 (mod 32), gcd(5,32)=1 -> the
// 32 lanes' scalar reads hit 32 distinct banks. Qp reads are warp-uniform
// broadcasts.
// ---------------------------------------------------------------------------
#define DPS 129
__global__ __launch_bounds__(256) void score_kernel(
    const float* __restrict__ gumbel,
    const float* __restrict__ q_mask,
    const float* __restrict__ d_mask,
    float* __restrict__ out)
{
    extern __shared__ float smem[];
    float* Dp_s    = smem;                    // [160][129]
    float* Qp_s    = Dp_s + NN * DPS;         // [32][128]
    float* dmask_s = Qp_s + MM * DIMV;        // [160]
    float* qmask_s = dmask_s + NN;            // [32]
    float* partial = qmask_s + MM;            // [8]

    const int bx   = blockIdx.x;              // q*200 + d
    const int d    = bx % ND_;
    const int q    = bx / ND_;
    const int tid  = threadIdx.x;
    const int warp = tid >> 5;                // 0..7 -> m group
    const int lane = tid & 31;                // -> n group

    // Load Dp[d]: 160x128 floats = 5120 float4, 20 per thread.
    {
        const float4* Dg = (const float4*)(g_Dp + (size_t)d * NN * DIMV);
#pragma unroll
        for (int it = 0; it < 20; it++) {
            int idx4 = tid + 256 * it;
            int n = idx4 >> 5, k4 = idx4 & 31;
            float4 v = Dg[idx4];
            float* dst = Dp_s + n * DPS + k4 * 4;
            dst[0] = v.x; dst[1] = v.y; dst[2] = v.z; dst[3] = v.w;
        }
    }
    // Load Qp[q]: 32x128 = 1024 float4, 4 per thread.
    {
        const float4* Qg = (const float4*)(g_Qp + (size_t)q * MM * DIMV);
#pragma unroll
        for (int it = 0; it < 4; it++) {
            int idx4 = tid + 256 * it;
            float4 v = Qg[idx4];
            float* dst = Qp_s + idx4 * 4;
            dst[0] = v.x; dst[1] = v.y; dst[2] = v.z; dst[3] = v.w;
        }
    }
    if (tid < NN) dmask_s[tid] = d_mask[(size_t)d * NN + tid];
    if (tid < MM) qmask_s[tid] = q_mask[(size_t)q * MM + tid];
    __syncthreads();

    // 4m x 5n register tile, k-loop over 128.
    float acc[4][5];
#pragma unroll
    for (int i = 0; i < 4; i++)
#pragma unroll
        for (int j = 0; j < 5; j++) acc[i][j] = 0.0f;

    const float* Qrow = Qp_s + (warp * 4) * DIMV;
    const float* Drow = Dp_s + (lane * 5) * DPS;

#pragma unroll 4
    for (int k = 0; k < DIMV; k++) {
        float a[4], b[5];
#pragma unroll
        for (int i = 0; i < 4; i++) a[i] = Qrow[i * DIMV + k];
#pragma unroll
        for (int j = 0; j < 5; j++) b[j] = Drow[j * DPS + k];
#pragma unroll
        for (int i = 0; i < 4; i++)
#pragma unroll
            for (int j = 0; j < 5; j++)
                acc[i][j] = fmaf(a[i], b[j], acc[i][j]);
    }

    // Epilogue: mask, add gumbel, argmax over n per m-row, weighted sum.
    const float* gb = gumbel + (size_t)bx * MM * NN;
    float psum = 0.0f;
#pragma unroll
    for (int i = 0; i < 4; i++) {
        const int m = warp * 4 + i;
        float bestz = -3.0e38f, bests = 0.0f;
#pragma unroll
        for (int j = 0; j < 5; j++) {
            const int n = lane * 5 + j;
            float dm = dmask_s[n];
            float sv = acc[i][j] * dm + (1.0f - dm) * NEGV;   // exact select
            float z  = sv * 10.0f + gb[m * NN + n];
            if (z > bestz) { bestz = z; bests = sv; }
        }
#pragma unroll
        for (int off = 16; off >= 1; off >>= 1) {
            float zo = __shfl_xor_sync(0xffffffffu, bestz, off);
            float so = __shfl_xor_sync(0xffffffffu, bests, off);
            if (zo > bestz) { bestz = zo; bests = so; }
        }
        psum += qmask_s[m] * bests;
    }
    if (lane == 0) partial[warp] = psum;
    __syncthreads();
    if (tid == 0) {
        float s = 0.0f;
#pragma unroll
        for (int w = 0; w < 8; w++) s += partial[w];
        out[bx] = s;
    }
}

// ---------------------------------------------------------------------------
extern "C" void kernel_launch(void* const* d_in, const int* in_sizes, int n_in,
                              void* d_out, int out_size)
{
    const float* Q      = (const float*)d_in[0];  // (32,32,768)
    const float* D      = (const float*)d_in[1];  // (200,160,768)
    const float* q_mask = (const float*)d_in[2];  // (32,32)
    const float* d_mask = (const float*)d_in[3];  // (200,160)
    const float* gumbel = (const float*)d_in[4];  // (32,200,32,160)
    const float* W      = (const float*)d_in[5];  // (768,128)
    float* out = (float*)d_out;                   // (32,200)

    float* Qp; cudaGetSymbolAddress((void**)&Qp, g_Qp);
    float* Dp; cudaGetSymbolAddress((void**)&Dp, g_Dp);

    // Projections (independent, same stream => serialized but tiny vs score).
    proj_kernel<<<(NQ * MM) / 64, 256>>>(Q, W, Qp);
    proj_kernel<<<(ND_ * NN) / 64, 256>>>(D, W, Dp);

    // Fused sim + gumbel-argmax + score.
    const int smem_bytes = (NN * DPS + MM * DIMV + NN + MM + 8) * sizeof(float);
    cudaFuncSetAttribute(score_kernel,
                         cudaFuncAttributeMaxDynamicSharedMemorySize, smem_bytes);
    score_kernel<<<NQ * ND_, 256, smem_bytes>>>(gumbel, q_mask, d_mask, out);
}